// round 15
// baseline (speedup 1.0000x reference)
#include <cuda_runtime.h>
#include <cuda_bf16.h>

#define Hc 128
#define Wc 128
#define Cc 16
#define Nc 128
#define TW 136          // tile row stride in floats
#define TRQ 36          // tile rows: 32 interior + 4 halo
#define THREADS 128
#define SEG 8           // output rows per thread

extern __shared__ float tile[];

__global__ void __launch_bounds__(THREADS, 8)
dirsum_kernel(const float* __restrict__ in, float* __restrict__ out) {
    const int b     = blockIdx.x;
    const int plane = b >> 2;          // n*C + c
    const int hbase = (b & 3) << 5;    // 0, 32, 64, 96
    const int tid   = threadIdx.x;

    float4* t4 = reinterpret_cast<float4*>(tile);
    const float4 z = make_float4(0.f, 0.f, 0.f, 0.f);

    // Side-halo columns: float4 index 0 and 33 of each 34-wide tile row.
    if (tid < TRQ * 2)
        t4[(tid >> 1) * (TW / 4) + (tid & 1) * 33] = z;

    // ---- interior fill (rows 0..35 incl. top/bottom halo rows), division-free ----
    const float4* src = reinterpret_cast<const float4*>(in + (size_t)plane * Hc * Wc);
    #pragma unroll 3
    for (int i = tid; i < TRQ * 32; i += THREADS) {
        const int row = i >> 5;
        const int q   = i & 31;
        const int g   = hbase + row - 2;           // global input row
        float4 v = z;
        if ((unsigned)g < (unsigned)Hc)
            v = src[g * 32 + q];
        t4[row * (TW / 4) + 1 + q] = v;
    }
    __syncthreads();

    const int n = plane / Cc;
    const int c = plane % Cc;
    float* __restrict__ ob = out + ((size_t)n * 4 * Cc + c) * (size_t)(Hc * Wc);
    const int dstep = Cc * Hc * Wc;

    // Thread owns columns [w, w+4) over local rows [h0, h0+SEG).
    const int lane = tid & 31;
    const int seg  = tid >> 5;        // 0..3
    const int w    = lane * 4;
    const int h0   = seg * SEG;

    // Ring: a[d][m] = input[r-2+d][w-2+m], m=0..8
    float a[5][9];
    #pragma unroll
    for (int d = 0; d < 4; ++d) {
        const float* r = &tile[(h0 + d) * TW + w];
        const float4 v0 = *reinterpret_cast<const float4*>(r);
        const float4 v1 = *reinterpret_cast<const float4*>(r + 4);
        const float4 v2 = *reinterpret_cast<const float4*>(r + 8);
        a[d][0] = v0.z; a[d][1] = v0.w;
        a[d][2] = v1.x; a[d][3] = v1.y; a[d][4] = v1.z; a[d][5] = v1.w;
        a[d][6] = v2.x; a[d][7] = v2.y; a[d][8] = v2.z;
    }

    int oo = (hbase + h0) * Wc + w;

    #pragma unroll
    for (int i = 0; i < SEG; ++i) {
        // load the one new ring row (tile row h0+i+4)
        {
            const float* r = &tile[(h0 + i + 4) * TW + w];
            const float4 v0 = *reinterpret_cast<const float4*>(r);
            const float4 v1 = *reinterpret_cast<const float4*>(r + 4);
            const float4 v2 = *reinterpret_cast<const float4*>(r + 8);
            a[4][0] = v0.z; a[4][1] = v0.w;
            a[4][2] = v1.x; a[4][3] = v1.y; a[4][4] = v1.z; a[4][5] = v1.w;
            a[4][6] = v2.x; a[4][7] = v2.y; a[4][8] = v2.z;
        }

        // horizontal
        {
            const float r0 = a[2][0] + a[2][1] + a[2][2] + a[2][3] + a[2][4];
            const float r1 = a[2][1] + a[2][2] + a[2][3] + a[2][4] + a[2][5];
            const float r2 = a[2][2] + a[2][3] + a[2][4] + a[2][5] + a[2][6];
            const float r3 = a[2][3] + a[2][4] + a[2][5] + a[2][6] + a[2][7];
            __stcs(reinterpret_cast<float4*>(ob + oo), make_float4(r0, r1, r2, r3));
        }
        // vertical
        {
            const float r0 = a[0][2] + a[1][2] + a[2][2] + a[3][2] + a[4][2];
            const float r1 = a[0][3] + a[1][3] + a[2][3] + a[3][3] + a[4][3];
            const float r2 = a[0][4] + a[1][4] + a[2][4] + a[3][4] + a[4][4];
            const float r3 = a[0][5] + a[1][5] + a[2][5] + a[3][5] + a[4][5];
            __stcs(reinterpret_cast<float4*>(ob + dstep + oo), make_float4(r0, r1, r2, r3));
        }
        // main diag
        {
            const float r0 = a[0][0] + a[1][1] + a[2][2] + a[3][3] + a[4][4];
            const float r1 = a[0][1] + a[1][2] + a[2][3] + a[3][4] + a[4][5];
            const float r2 = a[0][2] + a[1][3] + a[2][4] + a[3][5] + a[4][6];
            const float r3 = a[0][3] + a[1][4] + a[2][5] + a[3][6] + a[4][7];
            __stcs(reinterpret_cast<float4*>(ob + 2 * dstep + oo), make_float4(r0, r1, r2, r3));
        }
        // anti diag
        {
            const float r0 = a[0][4] + a[1][3] + a[2][2] + a[3][1] + a[4][0];
            const float r1 = a[0][5] + a[1][4] + a[2][3] + a[3][2] + a[4][1];
            const float r2 = a[0][6] + a[1][5] + a[2][4] + a[3][3] + a[4][2];
            const float r3 = a[0][7] + a[1][6] + a[2][5] + a[3][4] + a[4][3];
            __stcs(reinterpret_cast<float4*>(ob + 3 * dstep + oo), make_float4(r0, r1, r2, r3));
        }

        oo += Wc;

        // shift ring (unrolled -> register renaming)
        #pragma unroll
        for (int d = 0; d < 4; ++d)
            #pragma unroll
            for (int m = 0; m < 9; ++m)
                a[d][m] = a[d + 1][m];
    }
}

extern "C" void kernel_launch(void* const* d_in, const int* in_sizes, int n_in,
                              void* d_out, int out_size) {
    const float* in = (const float*)d_in[0];
    float* out = (float*)d_out;
    const size_t smem = (size_t)TRQ * TW * sizeof(float);   // 19584 B
    cudaFuncSetAttribute(dirsum_kernel, cudaFuncAttributeMaxDynamicSharedMemorySize, (int)smem);
    dirsum_kernel<<<Nc * Cc * 4, THREADS, smem>>>(in, out);
}

// round 16
// speedup vs baseline: 1.0113x; 1.0113x over previous
#include <cuda_runtime.h>
#include <cuda_bf16.h>

#define Hc 128
#define Wc 128
#define Cc 16
#define Nc 128
#define TW 136          // tile row stride in floats
#define TRQ 36          // tile rows: 32 interior + 4 halo
#define THREADS 128
#define SEG 8           // output rows per thread

extern __shared__ float tile[];

__global__ void __launch_bounds__(THREADS, 8)
dirsum_kernel(const float* __restrict__ in, float* __restrict__ out) {
    const int b     = blockIdx.x;
    const int plane = b >> 2;          // n*C + c
    const int hbase = (b & 3) << 5;    // 0, 32, 64, 96
    const int tid   = threadIdx.x;

    float4* t4 = reinterpret_cast<float4*>(tile);
    const float4 z = make_float4(0.f, 0.f, 0.f, 0.f);

    // Side-halo columns: float4 index 0 and 33 of each 34-wide tile row.
    if (tid < TRQ * 2)
        t4[(tid >> 1) * (TW / 4) + (tid & 1) * 33] = z;

    // ---- interior fill (rows 0..35 incl. top/bottom halo rows), division-free ----
    const float4* src = reinterpret_cast<const float4*>(in + (size_t)plane * Hc * Wc);
    #pragma unroll 3
    for (int i = tid; i < TRQ * 32; i += THREADS) {
        const int row = i >> 5;
        const int q   = i & 31;
        const int g   = hbase + row - 2;           // global input row
        float4 v = z;
        if ((unsigned)g < (unsigned)Hc)
            v = src[g * 32 + q];
        t4[row * (TW / 4) + 1 + q] = v;
    }
    __syncthreads();

    const int n = plane / Cc;
    const int c = plane % Cc;
    float* __restrict__ ob = out + ((size_t)n * 4 * Cc + c) * (size_t)(Hc * Wc);
    const int dstep = Cc * Hc * Wc;

    // Thread owns columns [w, w+4) over local rows [h0, h0+SEG).
    const int lane = tid & 31;
    const int seg  = tid >> 5;        // 0..3
    const int w    = lane * 4;
    const int h0   = seg * SEG;

    // Ring: a[d][m] = input[r-2+d][w-2+m], m=0..8
    float a[5][9];
    #pragma unroll
    for (int d = 0; d < 4; ++d) {
        const float* r = &tile[(h0 + d) * TW + w];
        const float4 v0 = *reinterpret_cast<const float4*>(r);
        const float4 v1 = *reinterpret_cast<const float4*>(r + 4);
        const float4 v2 = *reinterpret_cast<const float4*>(r + 8);
        a[d][0] = v0.z; a[d][1] = v0.w;
        a[d][2] = v1.x; a[d][3] = v1.y; a[d][4] = v1.z; a[d][5] = v1.w;
        a[d][6] = v2.x; a[d][7] = v2.y; a[d][8] = v2.z;
    }

    int oo = (hbase + h0) * Wc + w;

    #pragma unroll
    for (int i = 0; i < SEG; ++i) {
        // load the one new ring row (tile row h0+i+4)
        {
            const float* r = &tile[(h0 + i + 4) * TW + w];
            const float4 v0 = *reinterpret_cast<const float4*>(r);
            const float4 v1 = *reinterpret_cast<const float4*>(r + 4);
            const float4 v2 = *reinterpret_cast<const float4*>(r + 8);
            a[4][0] = v0.z; a[4][1] = v0.w;
            a[4][2] = v1.x; a[4][3] = v1.y; a[4][4] = v1.z; a[4][5] = v1.w;
            a[4][6] = v2.x; a[4][7] = v2.y; a[4][8] = v2.z;
        }

        // horizontal
        {
            const float r0 = a[2][0] + a[2][1] + a[2][2] + a[2][3] + a[2][4];
            const float r1 = a[2][1] + a[2][2] + a[2][3] + a[2][4] + a[2][5];
            const float r2 = a[2][2] + a[2][3] + a[2][4] + a[2][5] + a[2][6];
            const float r3 = a[2][3] + a[2][4] + a[2][5] + a[2][6] + a[2][7];
            __stcs(reinterpret_cast<float4*>(ob + oo), make_float4(r0, r1, r2, r3));
        }
        // vertical
        {
            const float r0 = a[0][2] + a[1][2] + a[2][2] + a[3][2] + a[4][2];
            const float r1 = a[0][3] + a[1][3] + a[2][3] + a[3][3] + a[4][3];
            const float r2 = a[0][4] + a[1][4] + a[2][4] + a[3][4] + a[4][4];
            const float r3 = a[0][5] + a[1][5] + a[2][5] + a[3][5] + a[4][5];
            __stcs(reinterpret_cast<float4*>(ob + dstep + oo), make_float4(r0, r1, r2, r3));
        }
        // main diag
        {
            const float r0 = a[0][0] + a[1][1] + a[2][2] + a[3][3] + a[4][4];
            const float r1 = a[0][1] + a[1][2] + a[2][3] + a[3][4] + a[4][5];
            const float r2 = a[0][2] + a[1][3] + a[2][4] + a[3][5] + a[4][6];
            const float r3 = a[0][3] + a[1][4] + a[2][5] + a[3][6] + a[4][7];
            __stcs(reinterpret_cast<float4*>(ob + 2 * dstep + oo), make_float4(r0, r1, r2, r3));
        }
        // anti diag
        {
            const float r0 = a[0][4] + a[1][3] + a[2][2] + a[3][1] + a[4][0];
            const float r1 = a[0][5] + a[1][4] + a[2][3] + a[3][2] + a[4][1];
            const float r2 = a[0][6] + a[1][5] + a[2][4] + a[3][3] + a[4][2];
            const float r3 = a[0][7] + a[1][6] + a[2][5] + a[3][4] + a[4][3];
            __stcs(reinterpret_cast<float4*>(ob + 3 * dstep + oo), make_float4(r0, r1, r2, r3));
        }

        oo += Wc;

        // shift ring (unrolled -> register renaming)
        #pragma unroll
        for (int d = 0; d < 4; ++d)
            #pragma unroll
            for (int m = 0; m < 9; ++m)
                a[d][m] = a[d + 1][m];
    }
}

extern "C" void kernel_launch(void* const* d_in, const int* in_sizes, int n_in,
                              void* d_out, int out_size) {
    const float* in = (const float*)d_in[0];
    float* out = (float*)d_out;
    const size_t smem = (size_t)TRQ * TW * sizeof(float);   // 19584 B
    cudaFuncSetAttribute(dirsum_kernel, cudaFuncAttributeMaxDynamicSharedMemorySize, (int)smem);
    dirsum_kernel<<<Nc * Cc * 4, THREADS, smem>>>(in, out);
}

// round 17
// speedup vs baseline: 1.0168x; 1.0055x over previous
#include <cuda_runtime.h>
#include <cuda_bf16.h>

#define Hc 128
#define Wc 128
#define Cc 16
#define Nc 128
#define TW 136          // tile row stride in floats
#define TRQ 36          // tile rows: 32 interior + 4 halo
#define THREADS 128
#define SEG 8           // output rows per thread

extern __shared__ float tile[];

__global__ void __launch_bounds__(THREADS, 8)
dirsum_kernel(const float* __restrict__ in, float* __restrict__ out) {
    const int b     = blockIdx.x;
    const int plane = b >> 2;          // n*C + c
    const int hbase = (b & 3) << 5;    // 0, 32, 64, 96
    const int tid   = threadIdx.x;

    float4* t4 = reinterpret_cast<float4*>(tile);
    const float4 z = make_float4(0.f, 0.f, 0.f, 0.f);

    // Side-halo columns: float4 index 0 and 33 of each 34-wide tile row.
    if (tid < TRQ * 2)
        t4[(tid >> 1) * (TW / 4) + (tid & 1) * 33] = z;

    // ---- interior fill (rows 0..35 incl. top/bottom halo rows), division-free ----
    const float4* src = reinterpret_cast<const float4*>(in + (size_t)plane * Hc * Wc);
    #pragma unroll 3
    for (int i = tid; i < TRQ * 32; i += THREADS) {
        const int row = i >> 5;
        const int q   = i & 31;
        const int g   = hbase + row - 2;           // global input row
        float4 v = z;
        if ((unsigned)g < (unsigned)Hc)
            v = src[g * 32 + q];
        t4[row * (TW / 4) + 1 + q] = v;
    }
    __syncthreads();

    const int n = plane / Cc;
    const int c = plane % Cc;
    float* __restrict__ ob = out + ((size_t)n * 4 * Cc + c) * (size_t)(Hc * Wc);
    const int dstep = Cc * Hc * Wc;

    // Thread owns columns [w, w+4) over local rows [h0, h0+SEG).
    const int lane = tid & 31;
    const int seg  = tid >> 5;        // 0..3
    const int w    = lane * 4;
    const int h0   = seg * SEG;

    // Ring: a[d][m] = input[r-2+d][w-2+m], m=0..8
    float a[5][9];
    #pragma unroll
    for (int d = 0; d < 4; ++d) {
        const float* r = &tile[(h0 + d) * TW + w];
        const float4 v0 = *reinterpret_cast<const float4*>(r);
        const float4 v1 = *reinterpret_cast<const float4*>(r + 4);
        const float4 v2 = *reinterpret_cast<const float4*>(r + 8);
        a[d][0] = v0.z; a[d][1] = v0.w;
        a[d][2] = v1.x; a[d][3] = v1.y; a[d][4] = v1.z; a[d][5] = v1.w;
        a[d][6] = v2.x; a[d][7] = v2.y; a[d][8] = v2.z;
    }

    int oo = (hbase + h0) * Wc + w;

    #pragma unroll
    for (int i = 0; i < SEG; ++i) {
        // load the one new ring row (tile row h0+i+4)
        {
            const float* r = &tile[(h0 + i + 4) * TW + w];
            const float4 v0 = *reinterpret_cast<const float4*>(r);
            const float4 v1 = *reinterpret_cast<const float4*>(r + 4);
            const float4 v2 = *reinterpret_cast<const float4*>(r + 8);
            a[4][0] = v0.z; a[4][1] = v0.w;
            a[4][2] = v1.x; a[4][3] = v1.y; a[4][4] = v1.z; a[4][5] = v1.w;
            a[4][6] = v2.x; a[4][7] = v2.y; a[4][8] = v2.z;
        }

        // horizontal
        {
            const float r0 = a[2][0] + a[2][1] + a[2][2] + a[2][3] + a[2][4];
            const float r1 = a[2][1] + a[2][2] + a[2][3] + a[2][4] + a[2][5];
            const float r2 = a[2][2] + a[2][3] + a[2][4] + a[2][5] + a[2][6];
            const float r3 = a[2][3] + a[2][4] + a[2][5] + a[2][6] + a[2][7];
            __stcs(reinterpret_cast<float4*>(ob + oo), make_float4(r0, r1, r2, r3));
        }
        // vertical
        {
            const float r0 = a[0][2] + a[1][2] + a[2][2] + a[3][2] + a[4][2];
            const float r1 = a[0][3] + a[1][3] + a[2][3] + a[3][3] + a[4][3];
            const float r2 = a[0][4] + a[1][4] + a[2][4] + a[3][4] + a[4][4];
            const float r3 = a[0][5] + a[1][5] + a[2][5] + a[3][5] + a[4][5];
            __stcs(reinterpret_cast<float4*>(ob + dstep + oo), make_float4(r0, r1, r2, r3));
        }
        // main diag
        {
            const float r0 = a[0][0] + a[1][1] + a[2][2] + a[3][3] + a[4][4];
            const float r1 = a[0][1] + a[1][2] + a[2][3] + a[3][4] + a[4][5];
            const float r2 = a[0][2] + a[1][3] + a[2][4] + a[3][5] + a[4][6];
            const float r3 = a[0][3] + a[1][4] + a[2][5] + a[3][6] + a[4][7];
            __stcs(reinterpret_cast<float4*>(ob + 2 * dstep + oo), make_float4(r0, r1, r2, r3));
        }
        // anti diag
        {
            const float r0 = a[0][4] + a[1][3] + a[2][2] + a[3][1] + a[4][0];
            const float r1 = a[0][5] + a[1][4] + a[2][3] + a[3][2] + a[4][1];
            const float r2 = a[0][6] + a[1][5] + a[2][4] + a[3][3] + a[4][2];
            const float r3 = a[0][7] + a[1][6] + a[2][5] + a[3][4] + a[4][3];
            __stcs(reinterpret_cast<float4*>(ob + 3 * dstep + oo), make_float4(r0, r1, r2, r3));
        }

        oo += Wc;

        // shift ring (unrolled -> register renaming)
        #pragma unroll
        for (int d = 0; d < 4; ++d)
            #pragma unroll
            for (int m = 0; m < 9; ++m)
                a[d][m] = a[d + 1][m];
    }
}

extern "C" void kernel_launch(void* const* d_in, const int* in_sizes, int n_in,
                              void* d_out, int out_size) {
    const float* in = (const float*)d_in[0];
    float* out = (float*)d_out;
    const size_t smem = (size_t)TRQ * TW * sizeof(float);   // 19584 B
    cudaFuncSetAttribute(dirsum_kernel, cudaFuncAttributeMaxDynamicSharedMemorySize, (int)smem);
    dirsum_kernel<<<Nc * Cc * 4, THREADS, smem>>>(in, out);
}